// round 14
// baseline (speedup 1.0000x reference)
#include <cuda_runtime.h>
#include <cuda_fp16.h>
#include <cstdint>

#define NJ 14
#define NB 2
#define NT 32768
#define NH 128
#define CIN 131

// fragment-ordered fp16x2 weights: [j][l][kc(8)][nfpg(8)][lane(32)][q(4)]
__device__ uint32_t g_w16[NJ * 3 * 8192];
// fragment-ordered fp16x2 c tiles: [b][tile][w(8)][kc(8)][lane(32)][q(4)]
__device__ uint32_t g_cf[NB * 256 * 8192];

// ---------- helpers ----------
__device__ __forceinline__ void mma16816(float* d, const uint32_t* a,
                                         uint32_t b0, uint32_t b1) {
    asm volatile(
        "mma.sync.aligned.m16n8k16.row.col.f32.f16.f16.f32 "
        "{%0,%1,%2,%3}, {%4,%5,%6,%7}, {%8,%9}, {%0,%1,%2,%3};"
        : "+f"(d[0]), "+f"(d[1]), "+f"(d[2]), "+f"(d[3])
        : "r"(a[0]), "r"(a[1]), "r"(a[2]), "r"(a[3]), "r"(b0), "r"(b1));
}
__device__ __forceinline__ uint32_t h2bits(half2 h) {
    return *reinterpret_cast<uint32_t*>(&h);
}

// ---------- fused pre-conversion ----------
// blocks 0..41: weights -> B-fragment order (same as R13)
// blocks 42..553: c -> A-fragment order
__global__ void convert_all(const float* __restrict__ W0,
                            const float* __restrict__ W1,
                            const float* __restrict__ W2,
                            const float* __restrict__ c) {
    __shared__ uint32_t s[128 * 65];
    int bid = blockIdx.x;
    if (bid < 42) {
        int j = bid / 3, l = bid % 3;
        const float* W = (l == 0) ? W0 : ((l == 1) ? W1 : W2);
        int K = (l == 0) ? CIN : NH;
        int koff = (l == 0) ? 3 : 0;
        uint32_t* dst = g_w16 + (size_t)(j * 3 + l) * 8192;
        for (int i = threadIdx.x; i < 8192; i += blockDim.x) {
            // i = ((kc*8 + nfpg)*32 + lane)*4 + q
            int q = i & 3, lane = (i >> 2) & 31, nfpg = (i >> 7) & 7, kc = i >> 10;
            int n = nfpg * 16 + ((q >> 1) & 1) * 8 + (lane >> 2);
            int k = kc * 16 + (q & 1) * 8 + 2 * (lane & 3);
            const float* row = W + ((size_t)j * NH + n) * K + koff + k;
            dst[i] = h2bits(__floats2half2_rn(row[0], row[1]));
        }
    } else {
        int cid = bid - 42;
        int tile = cid & 255, b = cid >> 8;
        const float* cb = c + (size_t)b * NH * NT + tile * 128;
        uint32_t* dst = g_cf + ((size_t)b * 256 + tile) * 8192;
        // coalesced load + fp16 pack into smem: s[t][kw] = pack(c[2kw], c[2kw+1]) at t
        for (int i = threadIdx.x; i < 8192; i += 256) {
            int t = i & 127, kw = i >> 7;
            float v0 = __ldg(cb + (size_t)(2 * kw) * NT + t);
            float v1 = __ldg(cb + (size_t)(2 * kw + 1) * NT + t);
            s[t * 65 + kw] = h2bits(__floats2half2_rn(v0, v1));
        }
        __syncthreads();
        // write in A-fragment order: i = ((w*8 + kc)*32 + lane)*4 + q
        for (int i = threadIdx.x; i < 8192; i += 256) {
            int q = i & 3, lane = (i >> 2) & 31, kc = (i >> 7) & 7, w = i >> 10;
            int t  = w * 16 + (lane >> 2) + ((q & 1) ? 8 : 0);
            int kw = kc * 8 + (lane & 3) + ((q >> 1) ? 4 : 0);
            dst[i] = s[t * 65 + kw];
        }
    }
}

// ---------- main kernel: 8 warps, warp tile 16(M)x128(N), activations in registers ----------
__global__ __launch_bounds__(256, 2)
void ptf_hmma(const float* __restrict__ p,
              const float* __restrict__ ps,
              const float* __restrict__ b0g,
              const float* __restrict__ b1g,
              const float* __restrict__ b2g,
              const float* __restrict__ W0g,
              const float* __restrict__ W3g,
              const float* __restrict__ b3g,
              float* __restrict__ out) {
    __shared__ float bias_s[3 * 128];
    __shared__ float w0p_s[3 * 128];
    __shared__ float w3_s[128];

    const int tid = threadIdx.x, lane = tid & 31, wid = tid >> 5;
    const int t0 = blockIdx.x * 128, b = blockIdx.y, j = blockIdx.z;

    if (tid < 128) {
        bias_s[tid]       = __ldg(b0g + j * NH + tid);
        bias_s[128 + tid] = __ldg(b1g + j * NH + tid);
        bias_s[256 + tid] = __ldg(b2g + j * NH + tid);
        const float* w0r = W0g + ((size_t)j * NH + tid) * CIN;
        w0p_s[tid]       = __ldg(w0r);
        w0p_s[128 + tid] = __ldg(w0r + 1);
        w0p_s[256 + tid] = __ldg(w0r + 2);
        w3_s[tid] = __ldg(W3g + j * NH + tid);
    }
    __syncthreads();

    // B fragments (global, L1/L2-cached): + l*2048 + (kc*8 + g)*32
    const uint4* wf = (const uint4*)g_w16 + (size_t)(j * 3) * 2048 + lane;
    // layer-0 A fragments (pre-converted c): + kc*32
    const uint4* ca = (const uint4*)g_cf + ((size_t)b * 256 + blockIdx.x) * 2048
                      + (wid * 8) * 32 + lane;

    float acc[16][4];
    uint32_t ra[32];   // packed activations: ra[4*kc + q] = A-fragment reg q of chunk kc

    // ================= layer 0 (A from gmem fragments) =================
#pragma unroll
    for (int nf = 0; nf < 16; nf++)
#pragma unroll
        for (int q = 0; q < 4; q++) acc[nf][q] = 0.f;

#pragma unroll
    for (int kc = 0; kc < 8; kc++) {
        uint4 av = __ldg(ca + kc * 32);
        uint32_t a[4] = {av.x, av.y, av.z, av.w};
#pragma unroll
        for (int g = 0; g < 8; g++) {
            uint4 bw = __ldg(wf + (kc * 8 + g) * 32);
            mma16816(acc[2 * g],     a, bw.x, bw.y);
            mma16816(acc[2 * g + 1], a, bw.z, bw.w);
        }
    }

    // epilogue 0: bias + p rank-3 + relu -> ra
    {
        float pva[3], pvb[3];
        const int r0 = t0 + wid * 16 + (lane >> 2);
#pragma unroll
        for (int d = 0; d < 3; d++) {
            const float* pp = p + ((size_t)b * NJ * 3 + j * 3 + d) * NT;
            pva[d] = __ldg(pp + r0);
            pvb[d] = __ldg(pp + r0 + 8);
        }
#pragma unroll
        for (int nf = 0; nf < 16; nf++) {
            const int h = nf * 8 + 2 * (lane & 3);
            const float2 bb = *(const float2*)(bias_s + h);
            const float2 w0 = *(const float2*)(w0p_s + h);
            const float2 w1 = *(const float2*)(w0p_s + 128 + h);
            const float2 w2 = *(const float2*)(w0p_s + 256 + h);
            float v0 = acc[nf][0] + bb.x;
            float v1 = acc[nf][1] + bb.y;
            float v2 = acc[nf][2] + bb.x;
            float v3 = acc[nf][3] + bb.y;
            v0 = fmaf(pva[0], w0.x, v0); v1 = fmaf(pva[0], w0.y, v1);
            v2 = fmaf(pvb[0], w0.x, v2); v3 = fmaf(pvb[0], w0.y, v3);
            v0 = fmaf(pva[1], w1.x, v0); v1 = fmaf(pva[1], w1.y, v1);
            v2 = fmaf(pvb[1], w1.x, v2); v3 = fmaf(pvb[1], w1.y, v3);
            v0 = fmaf(pva[2], w2.x, v0); v1 = fmaf(pva[2], w2.y, v1);
            v2 = fmaf(pvb[2], w2.x, v2); v3 = fmaf(pvb[2], w2.y, v3);
            v0 = fmaxf(v0, 0.f); v1 = fmaxf(v1, 0.f);
            v2 = fmaxf(v2, 0.f); v3 = fmaxf(v3, 0.f);
            ra[2 * nf]     = h2bits(__floats2half2_rn(v0, v1));
            ra[2 * nf + 1] = h2bits(__floats2half2_rn(v2, v3));
        }
    }

    // ================= layers 1 & 2 (A from registers) =================
#pragma unroll
    for (int l = 1; l <= 2; l++) {
        const uint4* wfl = wf + (size_t)l * 2048;
#pragma unroll
        for (int nf = 0; nf < 16; nf++)
#pragma unroll
            for (int q = 0; q < 4; q++) acc[nf][q] = 0.f;

#pragma unroll
        for (int kc = 0; kc < 8; kc++) {
#pragma unroll
            for (int g = 0; g < 8; g++) {
                uint4 bw = __ldg(wfl + (kc * 8 + g) * 32);
                mma16816(acc[2 * g],     &ra[4 * kc], bw.x, bw.y);
                mma16816(acc[2 * g + 1], &ra[4 * kc], bw.z, bw.w);
            }
        }

        if (l == 1) {
            // epilogue 1: bias + relu -> ra
#pragma unroll
            for (int nf = 0; nf < 16; nf++) {
                const int h = nf * 8 + 2 * (lane & 3);
                const float2 bb = *(const float2*)(bias_s + 128 + h);
                float v0 = fmaxf(acc[nf][0] + bb.x, 0.f);
                float v1 = fmaxf(acc[nf][1] + bb.y, 0.f);
                float v2 = fmaxf(acc[nf][2] + bb.x, 0.f);
                float v3 = fmaxf(acc[nf][3] + bb.y, 0.f);
                ra[2 * nf]     = h2bits(__floats2half2_rn(v0, v1));
                ra[2 * nf + 1] = h2bits(__floats2half2_rn(v2, v3));
            }
        } else {
            // fused head: o[t] = relu(v) . W3, reduce within quad, atomic out
            float aL = 0.f, aH = 0.f;
#pragma unroll
            for (int nf = 0; nf < 16; nf++) {
                const int h = nf * 8 + 2 * (lane & 3);
                const float2 bb = *(const float2*)(bias_s + 256 + h);
                const float2 w3v = *(const float2*)(w3_s + h);
                float v0 = fmaxf(acc[nf][0] + bb.x, 0.f);
                float v1 = fmaxf(acc[nf][1] + bb.y, 0.f);
                float v2 = fmaxf(acc[nf][2] + bb.x, 0.f);
                float v3 = fmaxf(acc[nf][3] + bb.y, 0.f);
                aL += v0 * w3v.x + v1 * w3v.y;
                aH += v2 * w3v.x + v3 * w3v.y;
            }
            aL += __shfl_xor_sync(0xffffffffu, aL, 1);
            aL += __shfl_xor_sync(0xffffffffu, aL, 2);
            aH += __shfl_xor_sync(0xffffffffu, aH, 1);
            aH += __shfl_xor_sync(0xffffffffu, aH, 2);
            if ((lane & 3) == 0) {
                const float b3 = __ldg(b3g + j);
                const int t = t0 + wid * 16 + (lane >> 2);
                const float* psb = ps + ((size_t)b * NJ + j) * NT;
                float wL = __ldg(psb + t);
                float wH = __ldg(psb + t + 8);
                atomicAdd(out + (size_t)b * NT + t,     (aL + b3) * wL * (1.0f / 14.0f));
                atomicAdd(out + (size_t)b * NT + t + 8, (aH + b3) * wH * (1.0f / 14.0f));
            }
        }
    }
}

extern "C" void kernel_launch(void* const* d_in, const int* in_sizes, int n_in,
                              void* d_out, int out_size) {
    (void)in_sizes; (void)n_in;
    const float* p  = (const float*)d_in[0];
    // d_in[1] = z (unused by the reference)
    const float* c  = (const float*)d_in[2];
    const float* ps = (const float*)d_in[3];
    const float* W0 = (const float*)d_in[4];
    const float* b0 = (const float*)d_in[5];
    const float* W1 = (const float*)d_in[6];
    const float* b1 = (const float*)d_in[7];
    const float* W2 = (const float*)d_in[8];
    const float* b2 = (const float*)d_in[9];
    const float* W3 = (const float*)d_in[10];
    const float* b3 = (const float*)d_in[11];
    float* out = (float*)d_out;

    cudaMemsetAsync(out, 0, (size_t)out_size * sizeof(float));

    convert_all<<<554, 256>>>(W0, W1, W2, c);

    dim3 grid(NT / 128, NB, NJ);   // 256 x 2 x 14 = 7168 CTAs, j slowest
    ptf_hmma<<<grid, 256>>>(p, ps, b0, b1, b2, W0, W3, b3, out);
}